// round 1
// baseline (speedup 1.0000x reference)
#include <cuda_runtime.h>
#include <math.h>

#define Bn 4
#define Cn 128
#define Hn 128
#define Wn 128
#define On 128
#define Kn 9

// scratch: sampling coordinates + modulation mask, [B][K][H][W]
__device__ float g_py[Bn * Kn * Hn * Wn];
__device__ float g_px[Bn * Kn * Hn * Wn];
__device__ float g_m [Bn * Kn * Hn * Wn];

// ---------------------------------------------------------------------------
// Kernel 1: offset conv (in: concat(input,inter)=256ch, out: 27ch, 3x3, pad 1)
// fused with coordinate/mask transform.
// grid (H, B), block 128 (one thread per x).
// ---------------------------------------------------------------------------
__global__ __launch_bounds__(128) void dcn_offset_kernel(
    const float* __restrict__ inp,
    const float* __restrict__ inter,
    const float* __restrict__ offw,   // [27][256][3][3]
    const float* __restrict__ offb)   // [27]
{
    const int x = threadIdx.x;
    const int y = blockIdx.x;
    const int b = blockIdx.y;

    __shared__ float srow[8][3][132];   // 8 channels x 3 rows x (130 used)
    __shared__ float wsm[8 * 9 * 28];   // 8 ch x 9 k x 28 co (padded)

    float4 acc[7];
    {
        float ob[28];
        #pragma unroll
        for (int i = 0; i < 27; i++) ob[i] = offb[i];
        ob[27] = 0.f;
        #pragma unroll
        for (int q = 0; q < 7; q++)
            acc[q] = make_float4(ob[4*q], ob[4*q+1], ob[4*q+2], ob[4*q+3]);
    }

    for (int c0 = 0; c0 < 2 * Cn; c0 += 8) {
        __syncthreads();
        // fill feature rows for 8 channels (zero padding outside image)
        for (int i = x; i < 8 * 3 * 130; i += 128) {
            int ci  = i / 390;
            int rem = i - ci * 390;
            int r   = rem / 130;
            int xx  = rem - r * 130;
            int yg = y + r - 1;
            int xg = xx - 1;
            float v = 0.f;
            if (yg >= 0 && yg < Hn && xg >= 0 && xg < Wn) {
                int ch = c0 + ci;
                const float* base = (ch < Cn) ? inp : inter;
                int cc = (ch < Cn) ? ch : (ch - Cn);
                v = base[((b * Cn + cc) * Hn + yg) * Wn + xg];
            }
            srow[ci][r][xx] = v;
        }
        // fill weights, pad co=27 lane with 0
        for (int i = x; i < 8 * 9 * 28; i += 128) {
            int ci  = i / 252;
            int rem = i - ci * 252;
            int k   = rem / 28;
            int co  = rem - k * 28;
            float v = 0.f;
            if (co < 27) v = offw[co * 2304 + (c0 + ci) * 9 + k];
            wsm[(ci * 9 + k) * 28 + co] = v;
        }
        __syncthreads();

        #pragma unroll
        for (int ci = 0; ci < 8; ci++) {
            float f[9];
            #pragma unroll
            for (int k = 0; k < 9; k++)
                f[k] = srow[ci][k / 3][x + (k % 3)];
            #pragma unroll
            for (int k = 0; k < 9; k++) {
                const float4* w4 = (const float4*)&wsm[(ci * 9 + k) * 28];
                float fv = f[k];
                #pragma unroll
                for (int q = 0; q < 7; q++) {
                    float4 w = w4[q];
                    acc[q].x += fv * w.x;
                    acc[q].y += fv * w.y;
                    acc[q].z += fv * w.z;
                    acc[q].w += fv * w.w;
                }
            }
        }
    }

    float om[28];
    #pragma unroll
    for (int q = 0; q < 7; q++) {
        om[4*q+0] = acc[q].x; om[4*q+1] = acc[q].y;
        om[4*q+2] = acc[q].z; om[4*q+3] = acc[q].w;
    }

    // dy[k] = om[2k], dx[k] = om[2k+1], mask[k] = sigmoid(om[18+k])
    #pragma unroll
    for (int k = 0; k < 9; k++) {
        float dy = om[2 * k];
        float dx = om[2 * k + 1];
        float mv = 1.f / (1.f + expf(-om[18 + k]));
        int idx = ((b * Kn + k) * Hn + y) * Wn + x;
        g_py[idx] = dy + (float)(y - 1 + (k / 3));
        g_px[idx] = dx + (float)(x - 1 + (k % 3));
        g_m [idx] = mv;
    }
}

// ---------------------------------------------------------------------------
// Kernel 2: fused bilinear sampling + main GEMM
// out[b,o,y,x] = bias[o] + sum_{c,k} sample(input,b,c,py,px)*mask * W[o,c,k]
// grid (2, H, B): each block = 64 pixels (one half-row) x all 128 outputs.
// block 256 threads; thread tile = 8 o x 4 px.
// ---------------------------------------------------------------------------
__global__ __launch_bounds__(256) void dcn_main_kernel(
    const float* __restrict__ inp,
    const float* __restrict__ wgt,    // [128][128][9]
    const float* __restrict__ bias,   // [128]
    float* __restrict__ out)
{
    extern __shared__ float smem[];
    float4* cw   = (float4*)smem;                   // 576 float4 (corner weights)
    int4*   coff = (int4*)(smem + 576 * 4);         // 576 int4   (corner offsets)
    float*  wsmT = smem + 576 * 8;                  // 72 x 132 (weights, T)
    float*  colsm = wsmT + 72 * 132;                // 72 x 68  (col tile)

    const int tid  = threadIdx.x;
    const int tile = blockIdx.x;          // 0 or 1
    const int y    = blockIdx.y;
    const int b    = blockIdx.z;
    const int xg0  = tile * 64;

    // precompute per (k, px): 4 bilinear weights (mask+validity folded) and
    // 4 clamped plane offsets
    for (int e = tid; e < 576; e += 256) {
        int k  = e >> 6;
        int px = e & 63;
        int gi = ((b * Kn + k) * Hn + y) * Wn + xg0 + px;
        float pyv = g_py[gi];
        float pxv = g_px[gi];
        float mv  = g_m[gi];
        float y0f = floorf(pyv);
        float x0f = floorf(pxv);
        float wy = pyv - y0f;
        float wx = pxv - x0f;
        int y0 = (int)y0f;
        int x0 = (int)x0f;
        float vy0 = (y0 >= 0  && y0 <= Hn - 1) ? 1.f : 0.f;
        float vy1 = (y0 >= -1 && y0 <= Hn - 2) ? 1.f : 0.f;
        float vx0 = (x0 >= 0  && x0 <= Wn - 1) ? 1.f : 0.f;
        float vx1 = (x0 >= -1 && x0 <= Wn - 2) ? 1.f : 0.f;
        float w00 = (1.f - wy) * (1.f - wx) * mv * (vy0 * vx0);
        float w01 = (1.f - wy) * wx         * mv * (vy0 * vx1);
        float w10 = wy * (1.f - wx)         * mv * (vy1 * vx0);
        float w11 = wy * wx                 * mv * (vy1 * vx1);
        int y0c = min(max(y0, 0), Hn - 1);
        int y1c = min(max(y0 + 1, 0), Hn - 1);
        int x0c = min(max(x0, 0), Wn - 1);
        int x1c = min(max(x0 + 1, 0), Wn - 1);
        cw[e]   = make_float4(w00, w01, w10, w11);
        coff[e] = make_int4(y0c * Wn + x0c, y0c * Wn + x1c,
                            y1c * Wn + x0c, y1c * Wn + x1c);
    }

    float4 acc[8];
    #pragma unroll
    for (int i = 0; i < 8; i++) acc[i] = make_float4(0.f, 0.f, 0.f, 0.f);

    const int og = tid & 15;
    const int pg = tid >> 4;
    const int o0 = og * 8;
    const int p0 = pg * 4;

    for (int c0 = 0; c0 < Cn; c0 += 8) {
        __syncthreads();   // protects smem reuse; at c0=0 also fences coords
        // stage weights, transposed: wsmT[kk][o]
        for (int i = tid; i < 9216; i += 256) {
            int o = i / 72;
            int r = i - o * 72;
            wsmT[r * 132 + o] = wgt[o * 1152 + c0 * 9 + r];
        }
        // stage col tile: colsm[kk][px], kk = c'*9 + k
        for (int i = tid; i < 4608; i += 256) {
            int kk = i >> 6;
            int px = i & 63;
            int cq = kk / 9;
            int k  = kk - cq * 9;
            int e  = (k << 6) + px;
            float4 w  = cw[e];
            int4 off  = coff[e];
            const float* pl = inp + (b * Cn + c0 + cq) * (Hn * Wn);
            colsm[kk * 68 + px] = w.x * pl[off.x] + w.y * pl[off.y]
                                + w.z * pl[off.z] + w.w * pl[off.w];
        }
        __syncthreads();

        #pragma unroll 8
        for (int kk = 0; kk < 72; kk++) {
            float4 wa = *(const float4*)&wsmT[kk * 132 + o0];
            float4 wb = *(const float4*)&wsmT[kk * 132 + o0 + 4];
            float4 cv = *(const float4*)&colsm[kk * 68 + p0];
            acc[0].x += wa.x * cv.x; acc[0].y += wa.x * cv.y; acc[0].z += wa.x * cv.z; acc[0].w += wa.x * cv.w;
            acc[1].x += wa.y * cv.x; acc[1].y += wa.y * cv.y; acc[1].z += wa.y * cv.z; acc[1].w += wa.y * cv.w;
            acc[2].x += wa.z * cv.x; acc[2].y += wa.z * cv.y; acc[2].z += wa.z * cv.z; acc[2].w += wa.z * cv.w;
            acc[3].x += wa.w * cv.x; acc[3].y += wa.w * cv.y; acc[3].z += wa.w * cv.z; acc[3].w += wa.w * cv.w;
            acc[4].x += wb.x * cv.x; acc[4].y += wb.x * cv.y; acc[4].z += wb.x * cv.z; acc[4].w += wb.x * cv.w;
            acc[5].x += wb.y * cv.x; acc[5].y += wb.y * cv.y; acc[5].z += wb.y * cv.z; acc[5].w += wb.y * cv.w;
            acc[6].x += wb.z * cv.x; acc[6].y += wb.z * cv.y; acc[6].z += wb.z * cv.z; acc[6].w += wb.z * cv.w;
            acc[7].x += wb.w * cv.x; acc[7].y += wb.w * cv.y; acc[7].z += wb.w * cv.z; acc[7].w += wb.w * cv.w;
        }
    }

    // epilogue: add bias, store
    #pragma unroll
    for (int i = 0; i < 8; i++) {
        int o = o0 + i;
        float bo = bias[o];
        float4 r = acc[i];
        r.x += bo; r.y += bo; r.z += bo; r.w += bo;
        *(float4*)&out[((b * On + o) * Hn + y) * Wn + xg0 + p0] = r;
    }
}

// ---------------------------------------------------------------------------
extern "C" void kernel_launch(void* const* d_in, const int* in_sizes, int n_in,
                              void* d_out, int out_size)
{
    const float* inp   = (const float*)d_in[0];
    const float* inter = (const float*)d_in[1];
    const float* offw  = (const float*)d_in[2];
    const float* offb  = (const float*)d_in[3];
    const float* wgt   = (const float*)d_in[4];
    const float* bias  = (const float*)d_in[5];
    float* out = (float*)d_out;

    dcn_offset_kernel<<<dim3(Hn, Bn), 128>>>(inp, inter, offw, offb);

    size_t smem3 = (size_t)(576 * 8 + 72 * 132 + 72 * 68) * sizeof(float); // 76,032 B
    cudaFuncSetAttribute(dcn_main_kernel,
                         cudaFuncAttributeMaxDynamicSharedMemorySize, (int)smem3);
    dcn_main_kernel<<<dim3(2, Hn, Bn), 256, smem3>>>(inp, wgt, bias, out);
}

// round 3
// speedup vs baseline: 1.5787x; 1.5787x over previous
#include <cuda_runtime.h>
#include <cuda_bf16.h>
#include <math.h>
#include <stdint.h>

#define Bn 4
#define Cn 128
#define Hn 128
#define Wn 128
#define On 128
#define Kn 9
#define KKn 1152          // Cn * Kn

// scratch: sampling coordinates + modulation mask, [B][K][H][W]
__device__ float g_py[Bn * Kn * Hn * Wn];
__device__ float g_px[Bn * Kn * Hn * Wn];
__device__ float g_m [Bn * Kn * Hn * Wn];
// pre-split main weights, bf16 hi/lo, [O][KK] (kk = c*9+k contiguous)
__device__ __nv_bfloat16 g_whi[On * KKn];
__device__ __nv_bfloat16 g_wlo[On * KKn];

#define SWZ(o) ((o) ^ (((o) >> 3) & 0x70))

// ---------------------------------------------------------------------------
// Kernel 0: split main weights into bf16 hi/lo
// ---------------------------------------------------------------------------
__global__ void dcn_wsplit_kernel(const float* __restrict__ wgt) {
    int i = blockIdx.x * 256 + threadIdx.x;
    if (i < On * KKn) {
        float w = wgt[i];
        __nv_bfloat16 h = __float2bfloat16(w);
        g_whi[i] = h;
        g_wlo[i] = __float2bfloat16(w - __bfloat162float(h));
    }
}

// ---------------------------------------------------------------------------
// Kernel 1: offset conv (2C=256 -> 27ch, 3x3, pad 1) + coord/mask transform.
// 256 threads = 2 image rows per CTA (shared weight staging).
// ---------------------------------------------------------------------------
__global__ __launch_bounds__(256) void dcn_offset_kernel(
    const float* __restrict__ inp,
    const float* __restrict__ inter,
    const float* __restrict__ offw,   // [27][256][3][3]
    const float* __restrict__ offb)   // [27]
{
    const int x  = threadIdx.x & 127;
    const int rh = threadIdx.x >> 7;
    const int y  = blockIdx.x * 2 + rh;
    const int b  = blockIdx.y;

    __shared__ float srow[2][8][3][132];
    __shared__ float wsm[8 * 9 * 28];

    float4 acc[7];
    {
        float ob[28];
        #pragma unroll
        for (int i = 0; i < 27; i++) ob[i] = offb[i];
        ob[27] = 0.f;
        #pragma unroll
        for (int q = 0; q < 7; q++)
            acc[q] = make_float4(ob[4*q], ob[4*q+1], ob[4*q+2], ob[4*q+3]);
    }

    for (int c0 = 0; c0 < 2 * Cn; c0 += 8) {
        __syncthreads();
        // feature rows: each half-block fills rows for its own y
        for (int i = x; i < 8 * 3 * 130; i += 128) {
            int ci  = i / 390;
            int rem = i - ci * 390;
            int r   = rem / 130;
            int xx  = rem - r * 130;
            int yg = y + r - 1;
            int xg = xx - 1;
            float v = 0.f;
            if (yg >= 0 && yg < Hn && xg >= 0 && xg < Wn) {
                int ch = c0 + ci;
                const float* base = (ch < Cn) ? inp : inter;
                int cc = (ch < Cn) ? ch : (ch - Cn);
                v = base[((b * Cn + cc) * Hn + yg) * Wn + xg];
            }
            srow[rh][ci][r][xx] = v;
        }
        // weights (shared by both halves)
        for (int i = threadIdx.x; i < 8 * 9 * 28; i += 256) {
            int ci  = i / 252;
            int rem = i - ci * 252;
            int k   = rem / 28;
            int co  = rem - k * 28;
            float v = 0.f;
            if (co < 27) v = offw[co * 2304 + (c0 + ci) * 9 + k];
            wsm[(ci * 9 + k) * 28 + co] = v;
        }
        __syncthreads();

        #pragma unroll
        for (int ci = 0; ci < 8; ci++) {
            float f[9];
            #pragma unroll
            for (int k = 0; k < 9; k++)
                f[k] = srow[rh][ci][k / 3][x + (k % 3)];
            #pragma unroll
            for (int k = 0; k < 9; k++) {
                const float4* w4 = (const float4*)&wsm[(ci * 9 + k) * 28];
                float fv = f[k];
                #pragma unroll
                for (int q = 0; q < 7; q++) {
                    float4 w = w4[q];
                    acc[q].x += fv * w.x;
                    acc[q].y += fv * w.y;
                    acc[q].z += fv * w.z;
                    acc[q].w += fv * w.w;
                }
            }
        }
    }

    float om[28];
    #pragma unroll
    for (int q = 0; q < 7; q++) {
        om[4*q+0] = acc[q].x; om[4*q+1] = acc[q].y;
        om[4*q+2] = acc[q].z; om[4*q+3] = acc[q].w;
    }

    #pragma unroll
    for (int k = 0; k < 9; k++) {
        float dy = om[2 * k];
        float dx = om[2 * k + 1];
        float mv = 1.f / (1.f + expf(-om[18 + k]));
        int idx = ((b * Kn + k) * Hn + y) * Wn + x;
        g_py[idx] = dy + (float)(y - 1 + (k / 3));
        g_px[idx] = dx + (float)(x - 1 + (k % 3));
        g_m [idx] = mv;
    }
}

// ---------------------------------------------------------------------------
// Kernel 2: warp-level HMMA (mma.sync bf16) main GEMM fused with bilinear
// gather. One CTA = one (b,y) row: D[o=128][px=128] in registers across 8
// warps (each 32o x 64px). K=1152 in 18 chunks of 64, double-buffered SMEM
// tiles (Ah/Al/Bh/Bl, SW128-swizzled), gather for chunk c+1 issued before
// MMAs of chunk c.
// ---------------------------------------------------------------------------
__device__ __forceinline__ uint32_t lds32(const char* p) {
    return *(const uint32_t*)p;
}
__device__ __forceinline__ void mma16816(float* d, uint32_t a0, uint32_t a1,
                                         uint32_t a2, uint32_t a3,
                                         uint32_t b0, uint32_t b1) {
    asm volatile(
        "mma.sync.aligned.m16n8k16.row.col.f32.bf16.bf16.f32 "
        "{%0,%1,%2,%3}, {%4,%5,%6,%7}, {%8,%9}, {%0,%1,%2,%3};"
        : "+f"(d[0]), "+f"(d[1]), "+f"(d[2]), "+f"(d[3])
        : "r"(a0), "r"(a1), "r"(a2), "r"(a3), "r"(b0), "r"(b1));
}

__global__ __launch_bounds__(256) void dcn_main_mma(
    const float* __restrict__ inp,
    const float* __restrict__ bias,
    float* __restrict__ out)
{
    extern __shared__ char smem_raw[];
    char* tiles = (char*)(((uintptr_t)smem_raw + 1023) & ~(uintptr_t)1023);
    // per-buffer (s=0/1, stride 64KB): Ah +0, Al +16K, Bh +32K, Bl +48K
    float4* cwgt  = (float4*)(tiles + 131072);           // [9*128]
    int*    cbase = (int*)   (tiles + 131072 + 18432);   // [9*128]
    int*    cstep = cbase + 1152;                        // [9*128]

    const int tid = threadIdx.x;
    const int wid = tid >> 5;
    const int lid = tid & 31;
    const int y   = blockIdx.x;
    const int b   = blockIdx.y;
    const int g   = lid >> 2;
    const int t   = lid & 3;
    const int m0  = (wid & 3) * 32;     // warp's o base
    const int n0  = (wid >> 2) * 64;    // warp's px base

    // corner precompute: per (k, px): 4 bilinear weights (mask+validity
    // folded) + base offset + packed steps
    for (int e = tid; e < 1152; e += 256) {
        int k  = e >> 7;
        int px = e & 127;
        int gi = ((b * Kn + k) * Hn + y) * Wn + px;
        float pyv = g_py[gi];
        float pxv = g_px[gi];
        float mv  = g_m[gi];
        float y0f = floorf(pyv);
        float x0f = floorf(pxv);
        float wy = pyv - y0f;
        float wx = pxv - x0f;
        int y0 = (int)y0f;
        int x0 = (int)x0f;
        float vy0 = (y0 >= 0  && y0 <= Hn - 1) ? 1.f : 0.f;
        float vy1 = (y0 >= -1 && y0 <= Hn - 2) ? 1.f : 0.f;
        float vx0 = (x0 >= 0  && x0 <= Wn - 1) ? 1.f : 0.f;
        float vx1 = (x0 >= -1 && x0 <= Wn - 2) ? 1.f : 0.f;
        float w00 = (1.f - wy) * (1.f - wx) * mv * (vy0 * vx0);
        float w01 = (1.f - wy) * wx         * mv * (vy0 * vx1);
        float w10 = wy * (1.f - wx)         * mv * (vy1 * vx0);
        float w11 = wy * wx                 * mv * (vy1 * vx1);
        int y0c = min(max(y0, 0), Hn - 1);
        int y1c = min(max(y0 + 1, 0), Hn - 1);
        int x0c = min(max(x0, 0), Wn - 1);
        int x1c = min(max(x0 + 1, 0), Wn - 1);
        cwgt[e]  = make_float4(w00, w01, w10, w11);
        cbase[e] = y0c * Wn + x0c;
        cstep[e] = (((y1c - y0c) * Wn) << 16) | (x1c - x0c);
    }
    __syncthreads();

    const float* binp = inp + (size_t)b * Cn * Hn * Wn;

    float acc[2][8][4];
    #pragma unroll
    for (int i = 0; i < 2; i++)
        #pragma unroll
        for (int j = 0; j < 8; j++)
            #pragma unroll
            for (int q = 0; q < 4; q++) acc[i][j][q] = 0.f;

    // ---- chunk fill (A: weight slices; B: bilinear-gathered cols) ----
    auto fill = [&](int chunk, char* buf) {
        // A tiles (hi/lo), 128 rows x 64 bf16 (=128B per row)
        #pragma unroll
        for (int i = tid; i < 2048; i += 256) {
            int tt = i >> 10;
            int r  = (i >> 3) & 127;
            int j  = i & 7;
            const char* src = (tt ? (const char*)g_wlo : (const char*)g_whi)
                              + r * 2304 + chunk * 128 + j * 16;
            uint4 v = *(const uint4*)src;
            uint32_t off = (uint32_t)(r * 128 + j * 16);
            *(uint4*)(buf + tt * 16384 + SWZ(off)) = v;
        }
        // B tiles (hi/lo), 128 px rows x 64 bf16
        #pragma unroll
        for (int i = tid; i < 1024; i += 256) {
            int px = i & 127;
            int jg = i >> 7;
            uint4 vh4, vl4;
            __nv_bfloat16* vh = (__nv_bfloat16*)&vh4;
            __nv_bfloat16* vl = (__nv_bfloat16*)&vl4;
            #pragma unroll
            for (int j = 0; j < 8; ++j) {
                int kk = chunk * 64 + jg * 8 + j;
                int c  = kk / 9;
                int k  = kk - c * 9;
                int e  = (k << 7) + px;
                float4 w = cwgt[e];
                int base = cbase[e];
                int st   = cstep[e];
                int dx  = st & 0xffff;
                int dyr = st >> 16;
                const float* pl = binp + (c << 14);
                float v = w.x * pl[base]
                        + w.y * pl[base + dx]
                        + w.z * pl[base + dyr]
                        + w.w * pl[base + dyr + dx];
                __nv_bfloat16 h = __float2bfloat16(v);
                vh[j] = h;
                vl[j] = __float2bfloat16(v - __bfloat162float(h));
            }
            uint32_t off = (uint32_t)(px * 128 + jg * 16);
            *(uint4*)(buf + 32768 + SWZ(off)) = vh4;
            *(uint4*)(buf + 49152 + SWZ(off)) = vl4;
        }
    };

    fill(0, tiles);
    __syncthreads();

    for (int c = 0; c < 18; ++c) {
        char* cur = tiles + (size_t)(c & 1) * 65536;
        if (c + 1 < 18) fill(c + 1, tiles + (size_t)((c + 1) & 1) * 65536);

        const char* Ah = cur;
        const char* Al = cur + 16384;
        const char* Bh = cur + 32768;
        const char* Bl = cur + 49152;

        #pragma unroll
        for (int ks = 0; ks < 4; ++ks) {
            uint32_t ah[2][4], al[2][4];
            #pragma unroll
            for (int mt = 0; mt < 2; ++mt) {
                uint32_t o0 = (uint32_t)((m0 + mt * 16 + g) * 128 + ks * 32 + 4 * t);
                ah[mt][0] = lds32(Ah + SWZ(o0));
                ah[mt][1] = lds32(Ah + SWZ(o0 + 1024));
                ah[mt][2] = lds32(Ah + SWZ(o0 + 16));
                ah[mt][3] = lds32(Ah + SWZ(o0 + 1040));
                al[mt][0] = lds32(Al + SWZ(o0));
                al[mt][1] = lds32(Al + SWZ(o0 + 1024));
                al[mt][2] = lds32(Al + SWZ(o0 + 16));
                al[mt][3] = lds32(Al + SWZ(o0 + 1040));
            }
            #pragma unroll
            for (int nt = 0; nt < 8; ++nt) {
                uint32_t ob = (uint32_t)((n0 + nt * 8 + g) * 128 + ks * 32 + 4 * t);
                uint32_t bh0 = lds32(Bh + SWZ(ob));
                uint32_t bh1 = lds32(Bh + SWZ(ob + 16));
                uint32_t bl0 = lds32(Bl + SWZ(ob));
                uint32_t bl1 = lds32(Bl + SWZ(ob + 16));
                #pragma unroll
                for (int mt = 0; mt < 2; ++mt) {
                    mma16816(acc[mt][nt], ah[mt][0], ah[mt][1], ah[mt][2], ah[mt][3], bh0, bh1);
                    mma16816(acc[mt][nt], ah[mt][0], ah[mt][1], ah[mt][2], ah[mt][3], bl0, bl1);
                    mma16816(acc[mt][nt], al[mt][0], al[mt][1], al[mt][2], al[mt][3], bh0, bh1);
                }
            }
        }
        __syncthreads();
    }

    // epilogue: add bias, store float2 pairs
    #pragma unroll
    for (int mt = 0; mt < 2; ++mt) {
        int r0 = m0 + mt * 16 + g;
        int r1 = r0 + 8;
        float bo0 = bias[r0];
        float bo1 = bias[r1];
        float* row0 = out + (((size_t)b * On + r0) * Hn + y) * Wn;
        float* row1 = out + (((size_t)b * On + r1) * Hn + y) * Wn;
        #pragma unroll
        for (int nt = 0; nt < 8; ++nt) {
            int cx = n0 + nt * 8 + 2 * t;
            float2 v0 = make_float2(acc[mt][nt][0] + bo0, acc[mt][nt][1] + bo0);
            float2 v1 = make_float2(acc[mt][nt][2] + bo1, acc[mt][nt][3] + bo1);
            *(float2*)(row0 + cx) = v0;
            *(float2*)(row1 + cx) = v1;
        }
    }
}

// ---------------------------------------------------------------------------
extern "C" void kernel_launch(void* const* d_in, const int* in_sizes, int n_in,
                              void* d_out, int out_size)
{
    const float* inp   = (const float*)d_in[0];
    const float* inter = (const float*)d_in[1];
    const float* offw  = (const float*)d_in[2];
    const float* offb  = (const float*)d_in[3];
    const float* wgt   = (const float*)d_in[4];
    const float* bias  = (const float*)d_in[5];
    float* out = (float*)d_out;

    dcn_wsplit_kernel<<<(On * KKn + 255) / 256, 256>>>(wgt);
    dcn_offset_kernel<<<dim3(Hn / 2, Bn), 256>>>(inp, inter, offw, offb);

    // 1024 align slack + 2*64KB tiles + corner tables
    size_t smem2 = 1024 + 131072 + 18432 + 4608 + 4608;   // 159,744 B
    cudaFuncSetAttribute(dcn_main_mma,
                         cudaFuncAttributeMaxDynamicSharedMemorySize, (int)smem2);
    dcn_main_mma<<<dim3(Hn, Bn), 256, smem2>>>(inp, bias, out);
}

// round 4
// speedup vs baseline: 1.8411x; 1.1662x over previous
#include <cuda_runtime.h>
#include <cuda_bf16.h>
#include <math.h>
#include <stdint.h>

#define Bn 4
#define Cn 128
#define Hn 128
#define Wn 128
#define On 128
#define Kn 9
#define KKn 1152          // Cn * Kn
#define OKK 4096          // offset conv padded K: 256 ch * 16

// scratch: sampling coordinates + modulation mask, [B][K][H][W]
__device__ float g_py[Bn * Kn * Hn * Wn];
__device__ float g_px[Bn * Kn * Hn * Wn];
__device__ float g_m [Bn * Kn * Hn * Wn];
// pre-split main weights, bf16 hi/lo, [O][KK] (kk = c*9+k contiguous)
__device__ __nv_bfloat16 g_whi[On * KKn];
__device__ __nv_bfloat16 g_wlo[On * KKn];
// pre-split offset-conv weights, bf16 hi/lo, [32][OKK] (kk2 = ch*16+k, padded)
__device__ __nv_bfloat16 g_owhi[32 * OKK];
__device__ __nv_bfloat16 g_owlo[32 * OKK];

#define SWZ(o) ((o) ^ (((o) >> 3) & 0x70))

__device__ __forceinline__ uint32_t lds32(const char* p) {
    return *(const uint32_t*)p;
}
__device__ __forceinline__ void mma16816(float* d, uint32_t a0, uint32_t a1,
                                         uint32_t a2, uint32_t a3,
                                         uint32_t b0, uint32_t b1) {
    asm volatile(
        "mma.sync.aligned.m16n8k16.row.col.f32.bf16.bf16.f32 "
        "{%0,%1,%2,%3}, {%4,%5,%6,%7}, {%8,%9}, {%0,%1,%2,%3};"
        : "+f"(d[0]), "+f"(d[1]), "+f"(d[2]), "+f"(d[3])
        : "r"(a0), "r"(a1), "r"(a2), "r"(a3), "r"(b0), "r"(b1));
}

// ---------------------------------------------------------------------------
// Kernel 0a: split main weights into bf16 hi/lo
// ---------------------------------------------------------------------------
__global__ void dcn_wsplit_kernel(const float* __restrict__ wgt) {
    int i = blockIdx.x * 256 + threadIdx.x;
    if (i < On * KKn) {
        float w = wgt[i];
        __nv_bfloat16 h = __float2bfloat16(w);
        g_whi[i] = h;
        g_wlo[i] = __float2bfloat16(w - __bfloat162float(h));
    }
}

// ---------------------------------------------------------------------------
// Kernel 0b: split + pad offset-conv weights into [32][4096] bf16 hi/lo
// ---------------------------------------------------------------------------
__global__ void dcn_owsplit_kernel(const float* __restrict__ offw) {
    int i = blockIdx.x * 256 + threadIdx.x;
    if (i >= 32 * OKK) return;
    int r   = i >> 12;
    int kk2 = i & (OKK - 1);
    int c4  = kk2 >> 4;
    int k   = kk2 & 15;
    float w = 0.f;
    if (r < 27 && k < 9) w = offw[r * 2304 + c4 * 9 + k];
    __nv_bfloat16 h = __float2bfloat16(w);
    g_owhi[i] = h;
    g_owlo[i] = __float2bfloat16(w - __bfloat162float(h));
}

// ---------------------------------------------------------------------------
// Kernel 1: offset conv via HMMA (27->32 rows padded, K=4096 padded) fused
// with coordinate/mask transform. One CTA per (b,y) row, 8 warps x 16 px.
// ---------------------------------------------------------------------------
__global__ __launch_bounds__(256) void dcn_offset_mma(
    const float* __restrict__ inp,
    const float* __restrict__ inter,
    const float* __restrict__ offb)
{
    extern __shared__ char smem_raw[];
    char* tiles = (char*)(((uintptr_t)smem_raw + 1023) & ~(uintptr_t)1023);
    // per buffer (stride 40960): Ah +0 (4K), Al +4096, Bh +8192 (16K), Bl +24576

    const int tid = threadIdx.x;
    const int wid = tid >> 5;
    const int lid = tid & 31;
    const int g   = lid >> 2;
    const int t   = lid & 3;
    const int y   = blockIdx.x;
    const int b   = blockIdx.y;
    const int n0  = wid * 16;

    float acc[2][2][4];
    #pragma unroll
    for (int i = 0; i < 2; i++)
        #pragma unroll
        for (int j = 0; j < 2; j++)
            #pragma unroll
            for (int q = 0; q < 4; q++) acc[i][j][q] = 0.f;

    auto fill = [&](int chunk, char* buf) {
        // A tiles (hi/lo): 32 rows x 64 bf16 (=128B per row)
        #pragma unroll
        for (int i = tid; i < 512; i += 256) {
            int tt = i >> 8;
            int r  = (i >> 3) & 31;
            int j  = i & 7;
            const char* src = (tt ? (const char*)g_owlo : (const char*)g_owhi)
                              + r * 8192 + chunk * 128 + j * 16;
            uint4 v = *(const uint4*)src;
            *(uint4*)(buf + tt * 4096 + SWZ((uint32_t)(r * 128 + j * 16))) = v;
        }
        // B tiles (hi/lo): 128 px rows x 64 bf16; kk2 = ch*16 + k
        #pragma unroll
        for (int i = tid; i < 1024; i += 256) {
            int px = i & 127;
            int jg = i >> 7;
            int ch = chunk * 4 + (jg >> 1);
            const float* base = (ch < Cn)
                ? inp   + ((size_t)b * Cn + ch) * (Hn * Wn)
                : inter + ((size_t)b * Cn + (ch - Cn)) * (Hn * Wn);
            int kbase = (jg & 1) * 8;
            uint4 vh4, vl4;
            __nv_bfloat16* vh = (__nv_bfloat16*)&vh4;
            __nv_bfloat16* vl = (__nv_bfloat16*)&vl4;
            #pragma unroll
            for (int j = 0; j < 8; ++j) {
                int k = kbase + j;
                float v = 0.f;
                if (k < 9) {
                    int ky = k / 3;
                    int kx = k - ky * 3;
                    int yg = y + ky - 1;
                    int xg = px + kx - 1;
                    if (yg >= 0 && yg < Hn && xg >= 0 && xg < Wn)
                        v = base[yg * Wn + xg];
                }
                __nv_bfloat16 h = __float2bfloat16(v);
                vh[j] = h;
                vl[j] = __float2bfloat16(v - __bfloat162float(h));
            }
            uint32_t off = (uint32_t)(px * 128 + jg * 16);
            *(uint4*)(buf + 8192  + SWZ(off)) = vh4;
            *(uint4*)(buf + 24576 + SWZ(off)) = vl4;
        }
    };

    fill(0, tiles);
    __syncthreads();

    for (int c = 0; c < 64; ++c) {
        char* cur = tiles + (size_t)(c & 1) * 40960;
        if (c + 1 < 64) fill(c + 1, tiles + (size_t)((c + 1) & 1) * 40960);

        const char* Ah = cur;
        const char* Al = cur + 4096;
        const char* Bh = cur + 8192;
        const char* Bl = cur + 24576;

        #pragma unroll
        for (int ks = 0; ks < 4; ++ks) {
            uint32_t ah[2][4], al[2][4];
            #pragma unroll
            for (int mt = 0; mt < 2; ++mt) {
                uint32_t o0 = (uint32_t)((mt * 16 + g) * 128 + ks * 32 + 4 * t);
                ah[mt][0] = lds32(Ah + SWZ(o0));
                ah[mt][1] = lds32(Ah + SWZ(o0 + 1024));
                ah[mt][2] = lds32(Ah + SWZ(o0 + 16));
                ah[mt][3] = lds32(Ah + SWZ(o0 + 1040));
                al[mt][0] = lds32(Al + SWZ(o0));
                al[mt][1] = lds32(Al + SWZ(o0 + 1024));
                al[mt][2] = lds32(Al + SWZ(o0 + 16));
                al[mt][3] = lds32(Al + SWZ(o0 + 1040));
            }
            #pragma unroll
            for (int nt = 0; nt < 2; ++nt) {
                uint32_t ob = (uint32_t)((n0 + nt * 8 + g) * 128 + ks * 32 + 4 * t);
                uint32_t bh0 = lds32(Bh + SWZ(ob));
                uint32_t bh1 = lds32(Bh + SWZ(ob + 16));
                uint32_t bl0 = lds32(Bl + SWZ(ob));
                uint32_t bl1 = lds32(Bl + SWZ(ob + 16));
                #pragma unroll
                for (int mt = 0; mt < 2; ++mt) {
                    mma16816(acc[mt][nt], ah[mt][0], ah[mt][1], ah[mt][2], ah[mt][3], bh0, bh1);
                    mma16816(acc[mt][nt], ah[mt][0], ah[mt][1], ah[mt][2], ah[mt][3], bl0, bl1);
                    mma16816(acc[mt][nt], al[mt][0], al[mt][1], al[mt][2], al[mt][3], bh0, bh1);
                }
            }
        }
        __syncthreads();
    }

    // epilogue 1: fragments -> smem D[32][132] (+ bias)
    float* Dsm = (float*)tiles;
    #pragma unroll
    for (int mt = 0; mt < 2; ++mt) {
        int r0 = mt * 16 + g;
        int r1 = r0 + 8;
        float bo0 = (r0 < 27) ? offb[r0] : 0.f;
        float bo1 = (r1 < 27) ? offb[r1] : 0.f;
        #pragma unroll
        for (int nt = 0; nt < 2; ++nt) {
            int cx = n0 + nt * 8 + 2 * t;
            Dsm[r0 * 132 + cx]     = acc[mt][nt][0] + bo0;
            Dsm[r0 * 132 + cx + 1] = acc[mt][nt][1] + bo0;
            Dsm[r1 * 132 + cx]     = acc[mt][nt][2] + bo1;
            Dsm[r1 * 132 + cx + 1] = acc[mt][nt][3] + bo1;
        }
    }
    __syncthreads();

    // epilogue 2: coordinate / mask transform
    if (tid < 128) {
        int x = tid;
        #pragma unroll
        for (int k = 0; k < 9; ++k) {
            float dy = Dsm[(2 * k) * 132 + x];
            float dx = Dsm[(2 * k + 1) * 132 + x];
            float mv = 1.f / (1.f + expf(-Dsm[(18 + k) * 132 + x]));
            int idx = ((b * Kn + k) * Hn + y) * Wn + x;
            g_py[idx] = dy + (float)(y - 1 + (k / 3));
            g_px[idx] = dx + (float)(x - 1 + (k % 3));
            g_m [idx] = mv;
        }
    }
}

// ---------------------------------------------------------------------------
// Kernel 2: warp-level HMMA main GEMM fused with bilinear gather (unchanged).
// ---------------------------------------------------------------------------
__global__ __launch_bounds__(256) void dcn_main_mma(
    const float* __restrict__ inp,
    const float* __restrict__ bias,
    float* __restrict__ out)
{
    extern __shared__ char smem_raw[];
    char* tiles = (char*)(((uintptr_t)smem_raw + 1023) & ~(uintptr_t)1023);
    float4* cwgt  = (float4*)(tiles + 131072);
    int*    cbase = (int*)   (tiles + 131072 + 18432);
    int*    cstep = cbase + 1152;

    const int tid = threadIdx.x;
    const int wid = tid >> 5;
    const int lid = tid & 31;
    const int y   = blockIdx.x;
    const int b   = blockIdx.y;
    const int g   = lid >> 2;
    const int t   = lid & 3;
    const int m0  = (wid & 3) * 32;
    const int n0  = (wid >> 2) * 64;

    for (int e = tid; e < 1152; e += 256) {
        int k  = e >> 7;
        int px = e & 127;
        int gi = ((b * Kn + k) * Hn + y) * Wn + px;
        float pyv = g_py[gi];
        float pxv = g_px[gi];
        float mv  = g_m[gi];
        float y0f = floorf(pyv);
        float x0f = floorf(pxv);
        float wy = pyv - y0f;
        float wx = pxv - x0f;
        int y0 = (int)y0f;
        int x0 = (int)x0f;
        float vy0 = (y0 >= 0  && y0 <= Hn - 1) ? 1.f : 0.f;
        float vy1 = (y0 >= -1 && y0 <= Hn - 2) ? 1.f : 0.f;
        float vx0 = (x0 >= 0  && x0 <= Wn - 1) ? 1.f : 0.f;
        float vx1 = (x0 >= -1 && x0 <= Wn - 2) ? 1.f : 0.f;
        float w00 = (1.f - wy) * (1.f - wx) * mv * (vy0 * vx0);
        float w01 = (1.f - wy) * wx         * mv * (vy0 * vx1);
        float w10 = wy * (1.f - wx)         * mv * (vy1 * vx0);
        float w11 = wy * wx                 * mv * (vy1 * vx1);
        int y0c = min(max(y0, 0), Hn - 1);
        int y1c = min(max(y0 + 1, 0), Hn - 1);
        int x0c = min(max(x0, 0), Wn - 1);
        int x1c = min(max(x0 + 1, 0), Wn - 1);
        cwgt[e]  = make_float4(w00, w01, w10, w11);
        cbase[e] = y0c * Wn + x0c;
        cstep[e] = (((y1c - y0c) * Wn) << 16) | (x1c - x0c);
    }
    __syncthreads();

    const float* binp = inp + (size_t)b * Cn * Hn * Wn;

    float acc[2][8][4];
    #pragma unroll
    for (int i = 0; i < 2; i++)
        #pragma unroll
        for (int j = 0; j < 8; j++)
            #pragma unroll
            for (int q = 0; q < 4; q++) acc[i][j][q] = 0.f;

    auto fill = [&](int chunk, char* buf) {
        #pragma unroll
        for (int i = tid; i < 2048; i += 256) {
            int tt = i >> 10;
            int r  = (i >> 3) & 127;
            int j  = i & 7;
            const char* src = (tt ? (const char*)g_wlo : (const char*)g_whi)
                              + r * 2304 + chunk * 128 + j * 16;
            uint4 v = *(const uint4*)src;
            uint32_t off = (uint32_t)(r * 128 + j * 16);
            *(uint4*)(buf + tt * 16384 + SWZ(off)) = v;
        }
        #pragma unroll
        for (int i = tid; i < 1024; i += 256) {
            int px = i & 127;
            int jg = i >> 7;
            uint4 vh4, vl4;
            __nv_bfloat16* vh = (__nv_bfloat16*)&vh4;
            __nv_bfloat16* vl = (__nv_bfloat16*)&vl4;
            #pragma unroll
            for (int j = 0; j < 8; ++j) {
                int kk = chunk * 64 + jg * 8 + j;
                int c  = kk / 9;
                int k  = kk - c * 9;
                int e  = (k << 7) + px;
                float4 w = cwgt[e];
                int base = cbase[e];
                int st   = cstep[e];
                int dx  = st & 0xffff;
                int dyr = st >> 16;
                const float* pl = binp + (c << 14);
                float v = w.x * pl[base]
                        + w.y * pl[base + dx]
                        + w.z * pl[base + dyr]
                        + w.w * pl[base + dyr + dx];
                __nv_bfloat16 h = __float2bfloat16(v);
                vh[j] = h;
                vl[j] = __float2bfloat16(v - __bfloat162float(h));
            }
            uint32_t off = (uint32_t)(px * 128 + jg * 16);
            *(uint4*)(buf + 32768 + SWZ(off)) = vh4;
            *(uint4*)(buf + 49152 + SWZ(off)) = vl4;
        }
    };

    fill(0, tiles);
    __syncthreads();

    for (int c = 0; c < 18; ++c) {
        char* cur = tiles + (size_t)(c & 1) * 65536;
        if (c + 1 < 18) fill(c + 1, tiles + (size_t)((c + 1) & 1) * 65536);

        const char* Ah = cur;
        const char* Al = cur + 16384;
        const char* Bh = cur + 32768;
        const char* Bl = cur + 49152;

        #pragma unroll
        for (int ks = 0; ks < 4; ++ks) {
            uint32_t ah[2][4], al[2][4];
            #pragma unroll
            for (int mt = 0; mt < 2; ++mt) {
                uint32_t o0 = (uint32_t)((m0 + mt * 16 + g) * 128 + ks * 32 + 4 * t);
                ah[mt][0] = lds32(Ah + SWZ(o0));
                ah[mt][1] = lds32(Ah + SWZ(o0 + 1024));
                ah[mt][2] = lds32(Ah + SWZ(o0 + 16));
                ah[mt][3] = lds32(Ah + SWZ(o0 + 1040));
                al[mt][0] = lds32(Al + SWZ(o0));
                al[mt][1] = lds32(Al + SWZ(o0 + 1024));
                al[mt][2] = lds32(Al + SWZ(o0 + 16));
                al[mt][3] = lds32(Al + SWZ(o0 + 1040));
            }
            #pragma unroll
            for (int nt = 0; nt < 8; ++nt) {
                uint32_t ob = (uint32_t)((n0 + nt * 8 + g) * 128 + ks * 32 + 4 * t);
                uint32_t bh0 = lds32(Bh + SWZ(ob));
                uint32_t bh1 = lds32(Bh + SWZ(ob + 16));
                uint32_t bl0 = lds32(Bl + SWZ(ob));
                uint32_t bl1 = lds32(Bl + SWZ(ob + 16));
                #pragma unroll
                for (int mt = 0; mt < 2; ++mt) {
                    mma16816(acc[mt][nt], ah[mt][0], ah[mt][1], ah[mt][2], ah[mt][3], bh0, bh1);
                    mma16816(acc[mt][nt], ah[mt][0], ah[mt][1], ah[mt][2], ah[mt][3], bl0, bl1);
                    mma16816(acc[mt][nt], al[mt][0], al[mt][1], al[mt][2], al[mt][3], bh0, bh1);
                }
            }
        }
        __syncthreads();
    }

    #pragma unroll
    for (int mt = 0; mt < 2; ++mt) {
        int r0 = m0 + mt * 16 + g;
        int r1 = r0 + 8;
        float bo0 = bias[r0];
        float bo1 = bias[r1];
        float* row0 = out + (((size_t)b * On + r0) * Hn + y) * Wn;
        float* row1 = out + (((size_t)b * On + r1) * Hn + y) * Wn;
        #pragma unroll
        for (int nt = 0; nt < 8; ++nt) {
            int cx = n0 + nt * 8 + 2 * t;
            float2 v0 = make_float2(acc[mt][nt][0] + bo0, acc[mt][nt][1] + bo0);
            float2 v1 = make_float2(acc[mt][nt][2] + bo1, acc[mt][nt][3] + bo1);
            *(float2*)(row0 + cx) = v0;
            *(float2*)(row1 + cx) = v1;
        }
    }
}

// ---------------------------------------------------------------------------
extern "C" void kernel_launch(void* const* d_in, const int* in_sizes, int n_in,
                              void* d_out, int out_size)
{
    const float* inp   = (const float*)d_in[0];
    const float* inter = (const float*)d_in[1];
    const float* offw  = (const float*)d_in[2];
    const float* offb  = (const float*)d_in[3];
    const float* wgt   = (const float*)d_in[4];
    const float* bias  = (const float*)d_in[5];
    float* out = (float*)d_out;

    dcn_wsplit_kernel<<<(On * KKn + 255) / 256, 256>>>(wgt);
    dcn_owsplit_kernel<<<(32 * OKK + 255) / 256, 256>>>(offw);

    size_t smem1 = 1024 + 2 * 40960;   // 82,944 B
    cudaFuncSetAttribute(dcn_offset_mma,
                         cudaFuncAttributeMaxDynamicSharedMemorySize, (int)smem1);
    dcn_offset_mma<<<dim3(Hn, Bn), 256, smem1>>>(inp, inter, offb);

    size_t smem2 = 1024 + 131072 + 18432 + 4608 + 4608;   // 159,744 B
    cudaFuncSetAttribute(dcn_main_mma,
                         cudaFuncAttributeMaxDynamicSharedMemorySize, (int)smem2);
    dcn_main_mma<<<dim3(Hn, Bn), 256, smem2>>>(inp, bias, out);
}

// round 5
// speedup vs baseline: 2.2541x; 1.2243x over previous
#include <cuda_runtime.h>
#include <cuda_bf16.h>
#include <math.h>
#include <stdint.h>

#define Bn 4
#define Cn 128
#define Hn 128
#define Wn 128
#define On 128
#define Kn 9
#define KKn 1152          // Cn * Kn   (main GEMM K)
#define OKK 2304          // offset conv K: 256 ch * 9, kk = c*9+k

// scratch: sampling coordinates + modulation mask, [B][K][H][W]
__device__ float g_py[Bn * Kn * Hn * Wn];
__device__ float g_px[Bn * Kn * Hn * Wn];
__device__ float g_m [Bn * Kn * Hn * Wn];
// pre-split main weights, bf16 hi/lo, [O][KK] (kk = c*9+k contiguous)
__device__ __nv_bfloat16 g_whi[On * KKn];
__device__ __nv_bfloat16 g_wlo[On * KKn];
// pre-split offset-conv weights, bf16 hi/lo, [32][OKK] (rows 27-31 zero)
__device__ __nv_bfloat16 g_owhi[32 * OKK];
__device__ __nv_bfloat16 g_owlo[32 * OKK];

#define SWZ(o) ((o) ^ (((o) >> 3) & 0x70))

__device__ __forceinline__ uint32_t smem_u32(const void* p) {
    uint32_t a;
    asm("{ .reg .u64 t; cvta.to.shared.u64 t, %1; cvt.u32.u64 %0, t; }"
        : "=r"(a) : "l"(p));
    return a;
}
__device__ __forceinline__ void ldsm4(uint32_t* r, uint32_t addr) {
    asm volatile("ldmatrix.sync.aligned.m8n8.x4.shared.b16 {%0,%1,%2,%3}, [%4];"
        : "=r"(r[0]), "=r"(r[1]), "=r"(r[2]), "=r"(r[3]) : "r"(addr));
}
__device__ __forceinline__ void mma16816(float* d, const uint32_t* a,
                                         uint32_t b0, uint32_t b1) {
    asm volatile(
        "mma.sync.aligned.m16n8k16.row.col.f32.bf16.bf16.f32 "
        "{%0,%1,%2,%3}, {%4,%5,%6,%7}, {%8,%9}, {%0,%1,%2,%3};"
        : "+f"(d[0]), "+f"(d[1]), "+f"(d[2]), "+f"(d[3])
        : "r"(a[0]), "r"(a[1]), "r"(a[2]), "r"(a[3]), "r"(b0), "r"(b1));
}

// ---------------------------------------------------------------------------
// Kernel 0a/0b: weight splits
// ---------------------------------------------------------------------------
__global__ void dcn_wsplit_kernel(const float* __restrict__ wgt) {
    int i = blockIdx.x * 256 + threadIdx.x;
    if (i < On * KKn) {
        float w = wgt[i];
        __nv_bfloat16 h = __float2bfloat16(w);
        g_whi[i] = h;
        g_wlo[i] = __float2bfloat16(w - __bfloat162float(h));
    }
}
__global__ void dcn_owsplit_kernel(const float* __restrict__ offw) {
    int i = blockIdx.x * 256 + threadIdx.x;
    if (i >= 32 * OKK) return;
    int r = i / OKK;
    float w = (r < 27) ? offw[i] : 0.f;       // offw is [27][2304], kk contiguous
    __nv_bfloat16 h = __float2bfloat16(w);
    g_owhi[i] = h;
    g_owlo[i] = __float2bfloat16(w - __bfloat162float(h));
}

// ---------------------------------------------------------------------------
// Kernel 1: offset conv via HMMA (32 padded rows x K=2304) + coord transform.
// One CTA per (b,y): 512 threads, 16 warps, warp tile 16o x 16px.
// ---------------------------------------------------------------------------
__global__ __launch_bounds__(512) void dcn_offset_mma(
    const float* __restrict__ inp,
    const float* __restrict__ inter,
    const float* __restrict__ offb)
{
    extern __shared__ char smem_raw[];
    char* tiles = (char*)(((uintptr_t)smem_raw + 1023) & ~(uintptr_t)1023);
    // per buffer (stride 40960): Ah +0 (4K), Al +4096, Bh +8192 (16K), Bl +24576

    const int tid = threadIdx.x;
    const int wid = tid >> 5;
    const int lid = tid & 31;
    const int g   = lid >> 2;
    const int t   = lid & 3;
    const int y   = blockIdx.x;
    const int b   = blockIdx.y;
    const int m0  = (wid & 1) * 16;
    const int n0  = (wid >> 1) * 16;

    const int idx = lid >> 3, lr = lid & 7;
    const uint32_t aoffb = (uint32_t)((m0 + (idx & 1) * 8 + lr) * 128 + (idx >> 1) * 16);
    const uint32_t boffb = (uint32_t)((n0 + (idx >> 1) * 8 + lr) * 128 + (idx & 1) * 16);
    const uint32_t tbase = smem_u32(tiles);

    float acc[2][4];
    #pragma unroll
    for (int j = 0; j < 2; j++)
        #pragma unroll
        for (int q = 0; q < 4; q++) acc[j][q] = 0.f;

    auto fill = [&](int chunk, char* buf) {
        // A tiles (hi/lo): 32 rows x 64 bf16
        {
            int i = tid;
            if (i < 512) {
                int tt = i >> 8;
                int r  = (i >> 3) & 31;
                int j  = i & 7;
                const char* src = (tt ? (const char*)g_owlo : (const char*)g_owhi)
                                  + r * (OKK * 2) + chunk * 128 + j * 16;
                uint4 v = *(const uint4*)src;
                *(uint4*)(buf + tt * 4096 + SWZ((uint32_t)(r * 128 + j * 16))) = v;
            }
        }
        // B tiles (hi/lo): 128 px rows x 64 bf16; kk = c*9 + k
        #pragma unroll
        for (int i = tid; i < 1024; i += 512) {
            int px = i & 127;
            int jg = i >> 7;
            uint4 vh4, vl4;
            __nv_bfloat16* vh = (__nv_bfloat16*)&vh4;
            __nv_bfloat16* vl = (__nv_bfloat16*)&vl4;
            #pragma unroll
            for (int j = 0; j < 8; ++j) {
                int kk = chunk * 64 + jg * 8 + j;
                int c  = kk / 9;
                int k  = kk - c * 9;
                int ky = k / 3;
                int kx = k - ky * 3;
                int yg = y + ky - 1;
                int xg = px + kx - 1;
                float v = 0.f;
                if (yg >= 0 && yg < Hn && xg >= 0 && xg < Wn) {
                    const float* base = (c < Cn)
                        ? inp   + ((size_t)b * Cn + c) * (Hn * Wn)
                        : inter + ((size_t)b * Cn + (c - Cn)) * (Hn * Wn);
                    v = base[yg * Wn + xg];
                }
                __nv_bfloat16 h = __float2bfloat16(v);
                vh[j] = h;
                vl[j] = __float2bfloat16(v - __bfloat162float(h));
            }
            uint32_t off = (uint32_t)(px * 128 + jg * 16);
            *(uint4*)(buf + 8192  + SWZ(off)) = vh4;
            *(uint4*)(buf + 24576 + SWZ(off)) = vl4;
        }
    };

    fill(0, tiles);
    __syncthreads();

    for (int c = 0; c < 36; ++c) {
        uint32_t cu = tbase + (uint32_t)((c & 1) * 40960);
        if (c + 1 < 36) fill(c + 1, tiles + (size_t)((c + 1) & 1) * 40960);

        uint32_t Ah = cu, Al = cu + 4096, Bh = cu + 8192, Bl = cu + 24576;
        #pragma unroll
        for (int ks = 0; ks < 4; ++ks) {
            uint32_t ah[4], al[4], bh[4], bl[4];
            uint32_t ao = SWZ(aoffb + ks * 32);
            uint32_t bo = SWZ(boffb + ks * 32);
            ldsm4(ah, Ah + ao);
            ldsm4(al, Al + ao);
            ldsm4(bh, Bh + bo);
            ldsm4(bl, Bl + bo);
            #pragma unroll
            for (int nt = 0; nt < 2; ++nt) {
                mma16816(acc[nt], ah, bh[2*nt], bh[2*nt+1]);
                mma16816(acc[nt], ah, bl[2*nt], bl[2*nt+1]);
                mma16816(acc[nt], al, bh[2*nt], bh[2*nt+1]);
            }
        }
        __syncthreads();
    }

    // epilogue 1: fragments -> smem D[32][132] (+ bias)
    float* Dsm = (float*)tiles;
    {
        int r0 = m0 + g;
        int r1 = r0 + 8;
        float bo0 = (r0 < 27) ? offb[r0] : 0.f;
        float bo1 = (r1 < 27) ? offb[r1] : 0.f;
        #pragma unroll
        for (int nt = 0; nt < 2; ++nt) {
            int cx = n0 + nt * 8 + 2 * t;
            Dsm[r0 * 132 + cx]     = acc[nt][0] + bo0;
            Dsm[r0 * 132 + cx + 1] = acc[nt][1] + bo0;
            Dsm[r1 * 132 + cx]     = acc[nt][2] + bo1;
            Dsm[r1 * 132 + cx + 1] = acc[nt][3] + bo1;
        }
    }
    __syncthreads();

    // epilogue 2: coordinate / mask transform
    if (tid < 128) {
        int x = tid;
        #pragma unroll
        for (int k = 0; k < 9; ++k) {
            float dy = Dsm[(2 * k) * 132 + x];
            float dx = Dsm[(2 * k + 1) * 132 + x];
            float mv = 1.f / (1.f + expf(-Dsm[(18 + k) * 132 + x]));
            int idx2 = ((b * Kn + k) * Hn + y) * Wn + x;
            g_py[idx2] = dy + (float)(y - 1 + (k / 3));
            g_px[idx2] = dx + (float)(x - 1 + (k % 3));
            g_m [idx2] = mv;
        }
    }
}

// ---------------------------------------------------------------------------
// Kernel 2: main GEMM (HMMA + ldmatrix) fused with bilinear gather.
// One CTA per (b,y): 512 threads, 16 warps, warp tile 32o x 32px.
// ---------------------------------------------------------------------------
__global__ __launch_bounds__(512) void dcn_main_mma(
    const float* __restrict__ inp,
    const float* __restrict__ bias,
    float* __restrict__ out)
{
    extern __shared__ char smem_raw[];
    char* tiles = (char*)(((uintptr_t)smem_raw + 1023) & ~(uintptr_t)1023);
    float4* cwgt  = (float4*)(tiles + 131072);           // [9*128]
    int*    cbase = (int*)   (tiles + 131072 + 18432);   // [9*128]
    int*    cstep = cbase + 1152;                        // [9*128]

    const int tid = threadIdx.x;
    const int wid = tid >> 5;
    const int lid = tid & 31;
    const int y   = blockIdx.x;
    const int b   = blockIdx.y;
    const int g   = lid >> 2;
    const int t   = lid & 3;
    const int m0  = (wid & 3) * 32;
    const int n0  = (wid >> 2) * 32;

    const int idx = lid >> 3, lr = lid & 7;
    const uint32_t aoffb0 = (uint32_t)((m0 + (idx & 1) * 8 + lr) * 128 + (idx >> 1) * 16);
    const uint32_t aoffb1 = aoffb0 + 16 * 128;
    const uint32_t boffb0 = (uint32_t)((n0 + (idx >> 1) * 8 + lr) * 128 + (idx & 1) * 16);
    const uint32_t boffb1 = boffb0 + 16 * 128;
    const uint32_t tbase  = smem_u32(tiles);

    // corner precompute
    for (int e = tid; e < 1152; e += 512) {
        int k  = e >> 7;
        int px = e & 127;
        int gi = ((b * Kn + k) * Hn + y) * Wn + px;
        float pyv = g_py[gi];
        float pxv = g_px[gi];
        float mv  = g_m[gi];
        float y0f = floorf(pyv);
        float x0f = floorf(pxv);
        float wy = pyv - y0f;
        float wx = pxv - x0f;
        int y0 = (int)y0f;
        int x0 = (int)x0f;
        float vy0 = (y0 >= 0  && y0 <= Hn - 1) ? 1.f : 0.f;
        float vy1 = (y0 >= -1 && y0 <= Hn - 2) ? 1.f : 0.f;
        float vx0 = (x0 >= 0  && x0 <= Wn - 1) ? 1.f : 0.f;
        float vx1 = (x0 >= -1 && x0 <= Wn - 2) ? 1.f : 0.f;
        float w00 = (1.f - wy) * (1.f - wx) * mv * (vy0 * vx0);
        float w01 = (1.f - wy) * wx         * mv * (vy0 * vx1);
        float w10 = wy * (1.f - wx)         * mv * (vy1 * vx0);
        float w11 = wy * wx                 * mv * (vy1 * vx1);
        int y0c = min(max(y0, 0), Hn - 1);
        int y1c = min(max(y0 + 1, 0), Hn - 1);
        int x0c = min(max(x0, 0), Wn - 1);
        int x1c = min(max(x0 + 1, 0), Wn - 1);
        cwgt[e]  = make_float4(w00, w01, w10, w11);
        cbase[e] = y0c * Wn + x0c;
        cstep[e] = (((y1c - y0c) * Wn) << 16) | (x1c - x0c);
    }
    __syncthreads();

    const float* binp = inp + (size_t)b * Cn * Hn * Wn;

    float acc[2][4][4];
    #pragma unroll
    for (int i = 0; i < 2; i++)
        #pragma unroll
        for (int j = 0; j < 4; j++)
            #pragma unroll
            for (int q = 0; q < 4; q++) acc[i][j][q] = 0.f;

    auto fill = [&](int chunk, char* buf) {
        // A tiles (hi/lo), 128 rows x 64 bf16
        #pragma unroll
        for (int i = tid; i < 2048; i += 512) {
            int tt = i >> 10;
            int r  = (i >> 3) & 127;
            int j  = i & 7;
            const char* src = (tt ? (const char*)g_wlo : (const char*)g_whi)
                              + r * 2304 + chunk * 128 + j * 16;
            uint4 v = *(const uint4*)src;
            uint32_t off = (uint32_t)(r * 128 + j * 16);
            *(uint4*)(buf + tt * 16384 + SWZ(off)) = v;
        }
        // B tiles (hi/lo), bilinear gather
        #pragma unroll
        for (int i = tid; i < 1024; i += 512) {
            int px = i & 127;
            int jg = i >> 7;
            uint4 vh4, vl4;
            __nv_bfloat16* vh = (__nv_bfloat16*)&vh4;
            __nv_bfloat16* vl = (__nv_bfloat16*)&vl4;
            #pragma unroll
            for (int j = 0; j < 8; ++j) {
                int kk = chunk * 64 + jg * 8 + j;
                int c  = kk / 9;
                int k  = kk - c * 9;
                int e  = (k << 7) + px;
                float4 w = cwgt[e];
                int base = cbase[e];
                int st   = cstep[e];
                int dx  = st & 0xffff;
                int dyr = st >> 16;
                const float* pl = binp + (c << 14);
                float v = w.x * pl[base]
                        + w.y * pl[base + dx]
                        + w.z * pl[base + dyr]
                        + w.w * pl[base + dyr + dx];
                __nv_bfloat16 h = __float2bfloat16(v);
                vh[j] = h;
                vl[j] = __float2bfloat16(v - __bfloat162float(h));
            }
            uint32_t off = (uint32_t)(px * 128 + jg * 16);
            *(uint4*)(buf + 32768 + SWZ(off)) = vh4;
            *(uint4*)(buf + 49152 + SWZ(off)) = vl4;
        }
    };

    fill(0, tiles);
    __syncthreads();

    for (int c = 0; c < 18; ++c) {
        uint32_t cu = tbase + (uint32_t)((c & 1) * 65536);
        if (c + 1 < 18) fill(c + 1, tiles + (size_t)((c + 1) & 1) * 65536);

        uint32_t Ah = cu, Al = cu + 16384, Bh = cu + 32768, Bl = cu + 49152;
        #pragma unroll
        for (int ks = 0; ks < 4; ++ks) {
            uint32_t ah[2][4], al[2][4], bh[2][4], bl[2][4];
            uint32_t ao0 = SWZ(aoffb0 + ks * 32);
            uint32_t ao1 = SWZ(aoffb1 + ks * 32);
            uint32_t bo0 = SWZ(boffb0 + ks * 32);
            uint32_t bo1 = SWZ(boffb1 + ks * 32);
            ldsm4(ah[0], Ah + ao0);
            ldsm4(ah[1], Ah + ao1);
            ldsm4(al[0], Al + ao0);
            ldsm4(al[1], Al + ao1);
            ldsm4(bh[0], Bh + bo0);
            ldsm4(bh[1], Bh + bo1);
            ldsm4(bl[0], Bl + bo0);
            ldsm4(bl[1], Bl + bo1);
            #pragma unroll
            for (int np = 0; np < 2; ++np) {
                #pragma unroll
                for (int hf = 0; hf < 2; ++hf) {
                    int nt = np * 2 + hf;
                    uint32_t b0h = bh[np][2*hf], b1h = bh[np][2*hf+1];
                    uint32_t b0l = bl[np][2*hf], b1l = bl[np][2*hf+1];
                    #pragma unroll
                    for (int mt = 0; mt < 2; ++mt) {
                        mma16816(acc[mt][nt], ah[mt], b0h, b1h);
                        mma16816(acc[mt][nt], ah[mt], b0l, b1l);
                        mma16816(acc[mt][nt], al[mt], b0h, b1h);
                    }
                }
            }
        }
        __syncthreads();
    }

    // epilogue: add bias, store float2 pairs
    #pragma unroll
    for (int mt = 0; mt < 2; ++mt) {
        int r0 = m0 + mt * 16 + g;
        int r1 = r0 + 8;
        float bo0 = bias[r0];
        float bo1 = bias[r1];
        float* row0 = out + (((size_t)b * On + r0) * Hn + y) * Wn;
        float* row1 = out + (((size_t)b * On + r1) * Hn + y) * Wn;
        #pragma unroll
        for (int nt = 0; nt < 4; ++nt) {
            int cx = n0 + nt * 8 + 2 * t;
            float2 v0 = make_float2(acc[mt][nt][0] + bo0, acc[mt][nt][1] + bo0);
            float2 v1 = make_float2(acc[mt][nt][2] + bo1, acc[mt][nt][3] + bo1);
            *(float2*)(row0 + cx) = v0;
            *(float2*)(row1 + cx) = v1;
        }
    }
}

// ---------------------------------------------------------------------------
extern "C" void kernel_launch(void* const* d_in, const int* in_sizes, int n_in,
                              void* d_out, int out_size)
{
    const float* inp   = (const float*)d_in[0];
    const float* inter = (const float*)d_in[1];
    const float* offw  = (const float*)d_in[2];
    const float* offb  = (const float*)d_in[3];
    const float* wgt   = (const float*)d_in[4];
    const float* bias  = (const float*)d_in[5];
    float* out = (float*)d_out;

    dcn_wsplit_kernel<<<(On * KKn + 255) / 256, 256>>>(wgt);
    dcn_owsplit_kernel<<<(32 * OKK + 255) / 256, 256>>>(offw);

    size_t smem1 = 1024 + 2 * 40960;   // 82,944 B
    cudaFuncSetAttribute(dcn_offset_mma,
                         cudaFuncAttributeMaxDynamicSharedMemorySize, (int)smem1);
    dcn_offset_mma<<<dim3(Hn, Bn), 512, smem1>>>(inp, inter, offb);

    size_t smem2 = 1024 + 131072 + 18432 + 4608 + 4608;   // 159,744 B
    cudaFuncSetAttribute(dcn_main_mma,
                         cudaFuncAttributeMaxDynamicSharedMemorySize, (int)smem2);
    dcn_main_mma<<<dim3(Hn, Bn), 512, smem2>>>(inp, bias, out);
}